// round 16
// baseline (speedup 1.0000x reference)
#include <cuda_runtime.h>
#include <cuda_fp16.h>
#include <cstdint>
#include <math.h>

#define BATCH  8
#define LSEQ   4096
#define HDIM   256
#define PDIM   256
#define MTOT   (BATCH*LSEQ)     /* 32768 */
#define CHUNK  64
#define NCHUNK (LSEQ/CHUNK)     /* 64 */
#define KC     512              /* complex-stacked width */

// GEMM tiling: BM=128, BN=256, warp tile 64x64 (8 warps = 2m x 4n)
#define BM 128
#define BN 256
#define BKT 32
#define PADROW 80               /* smem row stride bytes: 40 halves (32 + 8 pad) */
#define T_A 0u
#define T_B 10240u              /* A: 128*80 */
#define STAGE_BYTES 30720u      /* A 10240 + B 20480 */
#define NSLOT 3
#define SMEM_BYTES (NSLOT*STAGE_BYTES)   /* 92160 */

#define WSCALE   64.0f
#define WUNSCALE 0.015625f

// ---------------- scratch ---------------------------------------------------
__device__ __align__(1024) __half g_h [MTOT*HDIM];
__device__ __align__(1024) __half g_W [KC*HDIM];
__device__ __align__(1024) __half g_C [HDIM*KC];
__device__ __align__(1024) __half g_X [(size_t)MTOT*KC];
__device__ __align__(1024) __half g_bu[(size_t)MTOT*KC];   // fp16, x WSCALE
__device__ float g_ar[PDIM];
__device__ float g_ai[PDIM];
__device__ float g_gr[PDIM];
__device__ float g_gi[PDIM];
__device__ float g_Er[BATCH*NCHUNK*PDIM];
__device__ float g_Ei[BATCH*NCHUNK*PDIM];

// ---------------- PTX helpers (sm_80-class only: valid for .target sm_103) --
__device__ __forceinline__ uint32_t smem_u32(const void* p) {
    uint32_t a;
    asm("{ .reg .u64 t; cvta.to.shared.u64 t, %1; cvt.u32.u64 %0, t; }" : "=r"(a) : "l"(p));
    return a;
}
__device__ __forceinline__ void ldsm4(uint32_t* r, uint32_t addr) {
    asm volatile("ldmatrix.sync.aligned.m8n8.x4.shared.b16 {%0,%1,%2,%3}, [%4];"
        : "=r"(r[0]), "=r"(r[1]), "=r"(r[2]), "=r"(r[3]) : "r"(addr));
}
__device__ __forceinline__ void mma_f16(float* c, const uint32_t* a, const uint32_t* b) {
    asm volatile("mma.sync.aligned.m16n8k16.row.col.f32.f16.f16.f32 "
        "{%0,%1,%2,%3}, {%4,%5,%6,%7}, {%8,%9}, {%0,%1,%2,%3};"
        : "+f"(c[0]), "+f"(c[1]), "+f"(c[2]), "+f"(c[3])
        : "r"(a[0]), "r"(a[1]), "r"(a[2]), "r"(a[3]), "r"(b[0]), "r"(b[1]));
}
__device__ __forceinline__ void mma_f16acc(uint32_t* c, const uint32_t* a, const uint32_t* b) {
    asm volatile("mma.sync.aligned.m16n8k16.row.col.f16.f16.f16.f16 "
        "{%0,%1}, {%2,%3,%4,%5}, {%6,%7}, {%0,%1};"
        : "+r"(c[0]), "+r"(c[1])
        : "r"(a[0]), "r"(a[1]), "r"(a[2]), "r"(a[3]), "r"(b[0]), "r"(b[1]));
}
__device__ __forceinline__ float tanh_fast(float x) {
    float r; asm("tanh.approx.f32 %0, %1;" : "=f"(r) : "f"(x)); return r;
}
#define CP_COMMIT() asm volatile("cp.async.commit_group;" ::: "memory")
#define CP_WAIT(n)  asm volatile("cp.async.wait_group %0;" :: "n"(n) : "memory")

// ---------------- params: lambda_bar + gains only (1 block) ------------------
__global__ void k_params(const float* __restrict__ llr, const float* __restrict__ lim,
                         const float* __restrict__ ld)
{
    int p = threadIdx.x;
    double lr = -exp((double)llr[p]);
    double li = (double)lim[p];
    double d  = exp((double)ld[p]);
    double er = exp(lr * d);
    double ar = er * cos(li * d), ai = er * sin(li * d);
    g_ar[p] = (float)ar;
    g_ai[p] = (float)ai;
    double den = lr*lr + li*li;
    g_gr[p] = (float)(((ar - 1.0)*lr + ai*li) / den);
    g_gi[p] = (float)((ai*lr - (ar - 1.0)*li) / den);
}

// ---------------- parallel W/C fill (512 blocks) -----------------------------
__global__ void k_fill(const float* __restrict__ Btr, const float* __restrict__ Bti,
                       const float* __restrict__ Ctr, const float* __restrict__ Cti)
{
    int idx = blockIdx.x * 256 + threadIdx.x;       // 0 .. 131071
    {
        int row = idx >> 8, k = idx & 255, pp = row & 255;
        float gr = g_gr[pp], gi = g_gi[pp];
        float br = Btr[pp*HDIM + k], bi = Bti[pp*HDIM + k];
        float w = (row < 256) ? (gr*br - gi*bi) : (gr*bi + gi*br);
        g_W[idx] = __float2half(w * WSCALE);
    }
    {
        int h = idx >> 9, kk = idx & 511;
        float v = (kk < 256) ? Ctr[h*PDIM + kk] : -Cti[h*PDIM + (kk-256)];
        g_C[idx] = __float2half(v);
    }
}

// ---------------- LayerNorm -> fp16 ------------------------------------------
__global__ void k_ln(const float* __restrict__ u, const float* __restrict__ gamma,
                     const float* __restrict__ beta)
{
    int warp = threadIdx.x >> 5, lane = threadIdx.x & 31;
    int row  = blockIdx.x * 8 + warp;
    const float* ur = u + (size_t)row * HDIM;

    float v[8]; float sum = 0.f;
#pragma unroll
    for (int j = 0; j < 8; j++) { v[j] = ur[lane + 32*j]; sum += v[j]; }
#pragma unroll
    for (int o = 16; o; o >>= 1) sum += __shfl_xor_sync(0xffffffffu, sum, o);
    float mu = sum * (1.f/HDIM);

    float ss = 0.f;
#pragma unroll
    for (int j = 0; j < 8; j++) { float dd = v[j]-mu; ss += dd*dd; }
#pragma unroll
    for (int o = 16; o; o >>= 1) ss += __shfl_xor_sync(0xffffffffu, ss, o);
    float inv = rsqrtf(ss * (1.f/HDIM) + 1e-5f);

    size_t base = (size_t)row * HDIM;
#pragma unroll
    for (int j = 0; j < 8; j++) {
        int c = lane + 32*j;
        g_h[base + c] = __float2half((v[j]-mu) * inv * __ldg(&gamma[c]) + __ldg(&beta[c]));
    }
}

// ---------------- async tile loaders ----------------------------------------
// A: 128 rows x 32 halves
__device__ __forceinline__ void load_tileA_async(uint32_t dst_base,
        const __half* __restrict__ src, int row0, int ldk, int k0, int tid)
{
#pragma unroll
    for (int i = 0; i < 2; i++) {
        int ci = tid + i*256;              // 512 chunks of 16B
        int r = ci >> 2, cc = ci & 3;
        const __half* g = src + (size_t)(row0 + r)*ldk + k0 + cc*8;
        uint32_t d = dst_base + (uint32_t)(r*PADROW + cc*16);
        asm volatile("cp.async.cg.shared.global [%0], [%1], 16;" :: "r"(d), "l"(g));
    }
}
// B: 256 rows x 32 halves
__device__ __forceinline__ void load_tileB_async(uint32_t dst_base,
        const __half* __restrict__ src, int row0, int ldk, int k0, int tid)
{
#pragma unroll
    for (int i = 0; i < 4; i++) {
        int ci = tid + i*256;              // 1024 chunks of 16B
        int r = ci >> 2, cc = ci & 3;
        const __half* g = src + (size_t)(row0 + r)*ldk + k0 + cc*8;
        uint32_t d = dst_base + (uint32_t)(r*PADROW + cc*16);
        asm volatile("cp.async.cg.shared.global [%0], [%1], 16;" :: "r"(d), "l"(g));
    }
}

// ---------------- BK=32 sub-stage, 64x64 warp tile, fp16 acc -----------------
__device__ __forceinline__ void compute_stage_f16w(uint32_t sbase, int lane,
        int m_base, int n_base, uint32_t acc[4][8][2])
{
    int lane16 = lane & 15;
#pragma unroll
    for (int ks = 0; ks < 2; ks++) {
        uint32_t a[4][4], b[16];
#pragma unroll
        for (int mi = 0; mi < 4; mi++) {
            uint32_t off = (uint32_t)((m_base + mi*16 + lane16)*PADROW + ks*32 + (lane>>4)*16);
            ldsm4(a[mi], sbase + T_A + off);
        }
#pragma unroll
        for (int nn = 0; nn < 8; nn += 2) {
            uint32_t off = (uint32_t)((n_base + (nn + (lane>>4))*8 + (lane & 7))*PADROW
                                      + ks*32 + ((lane>>3)&1)*16);
            ldsm4(&b[nn*2], sbase + T_B + off);
        }
#pragma unroll
        for (int mi = 0; mi < 4; mi++)
#pragma unroll
            for (int ni = 0; ni < 8; ni++)
                mma_f16acc(acc[mi][ni], a[mi], &b[ni*2]);
    }
}

// ---------------- BK=32 sub-stage, 64x64 warp tile, fp32 acc -----------------
__device__ __forceinline__ void compute_stage_f32w(uint32_t sbase, int lane,
        int m_base, int n_base, float acc[4][8][4])
{
    int lane16 = lane & 15;
#pragma unroll
    for (int ks = 0; ks < 2; ks++) {
        uint32_t a[4][4], b[16];
#pragma unroll
        for (int mi = 0; mi < 4; mi++) {
            uint32_t off = (uint32_t)((m_base + mi*16 + lane16)*PADROW + ks*32 + (lane>>4)*16);
            ldsm4(a[mi], sbase + T_A + off);
        }
#pragma unroll
        for (int nn = 0; nn < 8; nn += 2) {
            uint32_t off = (uint32_t)((n_base + (nn + (lane>>4))*8 + (lane & 7))*PADROW
                                      + ks*32 + ((lane>>3)&1)*16);
            ldsm4(&b[nn*2], sbase + T_B + off);
        }
#pragma unroll
        for (int mi = 0; mi < 4; mi++)
#pragma unroll
            for (int ni = 0; ni < 8; ni++)
                mma_f16(acc[mi][ni], a[mi], &b[ni*2]);
    }
}

// ---------------- depth-3 pipeline helpers -----------------------------------
#define PIPE_PROLOGUE(A, B, ldk)                                            \
    load_tileA_async(sb + 0*STAGE_BYTES + T_A, A, bm, ldk, 0,   tid);       \
    load_tileB_async(sb + 0*STAGE_BYTES + T_B, B, bn, ldk, 0,   tid);       \
    CP_COMMIT();                                                            \
    load_tileA_async(sb + 1*STAGE_BYTES + T_A, A, bm, ldk, BKT, tid);       \
    load_tileB_async(sb + 1*STAGE_BYTES + T_B, B, bn, ldk, BKT, tid);       \
    CP_COMMIT();

#define PIPE_STEP(A, B, ldk, NIT, it)                                       \
    CP_WAIT(1);                                                             \
    __syncthreads();                                                        \
    {                                                                       \
        int pre = (it) + 2;                                                 \
        if (pre < (NIT)) {                                                  \
            uint32_t ss = sb + (uint32_t)(pre % NSLOT) * STAGE_BYTES;       \
            load_tileA_async(ss + T_A, A, bm, ldk, pre*BKT, tid);           \
            load_tileB_async(ss + T_B, B, bn, ldk, pre*BKT, tid);           \
        }                                                                   \
        CP_COMMIT();                                                        \
    }

// ---------------- GEMM1: g_bu = h @ W^T (fp16 acc, 64x64 tiles) --------------
__global__ __launch_bounds__(256, 2) void k_mgemm1()
{
    extern __shared__ char smem[];
    uint32_t sb = smem_u32(smem);
    int tid = threadIdx.x, wid = tid >> 5, lane = tid & 31;
    int bn = blockIdx.x * BN, bm = blockIdx.y * BM;
    int m_base = (wid & 1) * 64, n_base = (wid >> 1) * 64;

    uint32_t acc[4][8][2];
#pragma unroll
    for (int i = 0; i < 4; i++)
#pragma unroll
        for (int j = 0; j < 8; j++) { acc[i][j][0] = 0u; acc[i][j][1] = 0u; }

    const int NIT = HDIM / BKT;  // 8
    PIPE_PROLOGUE(g_h, g_W, HDIM)
    for (int it = 0; it < NIT; it++) {
        PIPE_STEP(g_h, g_W, HDIM, NIT, it)
        compute_stage_f16w(sb + (uint32_t)(it % NSLOT) * STAGE_BYTES, lane, m_base, n_base, acc);
    }

    int r0 = lane >> 2, c0 = (lane & 3) * 2;
#pragma unroll
    for (int mi = 0; mi < 4; mi++) {
        int mg = bm + m_base + mi*16 + r0;
#pragma unroll
        for (int ni = 0; ni < 8; ni++) {
            int cg = bn + n_base + ni*8 + c0;
            *(uint32_t*)&g_bu[(size_t)mg*KC + cg]     = acc[mi][ni][0];
            *(uint32_t*)&g_bu[(size_t)(mg+8)*KC + cg] = acc[mi][ni][1];
        }
    }
}

// ---------------- scan phase 1: chunk-end states (256t, 2 chunks/block) ------
__global__ void k_scan_ends()
{
    int tt = threadIdx.x;
    int c  = blockIdx.x * 2 + (tt >> 7);
    int t  = tt & 127;
    int b  = blockIdx.y;
    int pr = 2*t;
    float2 ar = *(const float2*)&g_ar[pr];
    float2 ai = *(const float2*)&g_ai[pr];
    size_t base = ((size_t)b * LSEQ + (size_t)c * CHUNK) * KC;
    float2 sr = make_float2(0.f, 0.f), si = make_float2(0.f, 0.f);
#pragma unroll 4
    for (int l = 0; l < CHUNK; l++) {
        float2 xr = __half22float2(*(const __half2*)&g_bu[base + (size_t)l*KC + pr]);
        float2 xi = __half22float2(*(const __half2*)&g_bu[base + (size_t)l*KC + 256 + pr]);
        float nrx = fmaf(ar.x, sr.x, fmaf(-ai.x, si.x, xr.x));
        float nix = fmaf(ar.x, si.x, fmaf( ai.x, sr.x, xi.x));
        float nry = fmaf(ar.y, sr.y, fmaf(-ai.y, si.y, xr.y));
        float niy = fmaf(ar.y, si.y, fmaf( ai.y, sr.y, xi.y));
        sr.x = nrx; si.x = nix; sr.y = nry; si.y = niy;
    }
    int idx = (b*NCHUNK + c)*PDIM + pr;
    *(float2*)&g_Er[idx] = sr;
    *(float2*)&g_Ei[idx] = si;
}

// ---------------- scan phase 2: carry chain ----------------------------------
__global__ void k_scan_chain()
{
    int p = threadIdx.x, b = blockIdx.x;
    float ar = g_ar[p], ai = g_ai[p];
    float tr = ar, ti = ai;
#pragma unroll
    for (int i = 0; i < 6; i++) { float nr = tr*tr - ti*ti; ti = 2.f*tr*ti; tr = nr; }
    float sr = 0.f, si = 0.f;
#pragma unroll 8
    for (int c = 0; c < NCHUNK; c++) {
        int idx = (b*NCHUNK + c)*PDIM + p;
        float er = g_Er[idx], ei = g_Ei[idx];
        g_Er[idx] = sr; g_Ei[idx] = si;
        float nr = fmaf(tr, sr, fmaf(-ti, si, er));
        si = fmaf(tr, si, fmaf( ti, sr, ei));
        sr = nr;
    }
}

// ---------------- scan phase 3: rescan, emit fp16 X --------------------------
__global__ void k_scan_write()
{
    int tt = threadIdx.x;
    int c  = blockIdx.x * 2 + (tt >> 7);
    int t  = tt & 127;
    int b  = blockIdx.y;
    int pr = 2*t;
    float2 ar = *(const float2*)&g_ar[pr];
    float2 ai = *(const float2*)&g_ai[pr];
    int cidx = (b*NCHUNK + c)*PDIM + pr;
    float2 sr = *(const float2*)&g_Er[cidx];
    float2 si = *(const float2*)&g_Ei[cidx];
    size_t base = ((size_t)b * LSEQ + (size_t)c * CHUNK) * KC;
#pragma unroll 4
    for (int l = 0; l < CHUNK; l++) {
        size_t o = base + (size_t)l*KC;
        float2 xr = __half22float2(*(const __half2*)&g_bu[o + pr]);
        float2 xi = __half22float2(*(const __half2*)&g_bu[o + 256 + pr]);
        float nrx = fmaf(ar.x, sr.x, fmaf(-ai.x, si.x, xr.x));
        float nix = fmaf(ar.x, si.x, fmaf( ai.x, sr.x, xi.x));
        float nry = fmaf(ar.y, sr.y, fmaf(-ai.y, si.y, xr.y));
        float niy = fmaf(ar.y, si.y, fmaf( ai.y, sr.y, xi.y));
        sr.x = nrx; si.x = nix; sr.y = nry; si.y = niy;
        *(__half2*)&g_X[o + pr]       = __floats2half2_rn(sr.x*WUNSCALE, sr.y*WUNSCALE);
        *(__half2*)&g_X[o + 256 + pr] = __floats2half2_rn(si.x*WUNSCALE, si.y*WUNSCALE);
    }
}

// ---------------- GEMM2: out = u + gelu(X @ C^T) (fp32 acc, 64x64) -----------
__device__ __forceinline__ float gelu_tanh(float x)
{
    float x3 = x*x*x;
    float t = tanh_fast(0.7978845608028654f * fmaf(0.044715f, x3, x));
    return 0.5f * x * (1.f + t);
}

__global__ __launch_bounds__(256, 1) void k_mgemm2(const float* __restrict__ U,
                                                   float* __restrict__ out)
{
    extern __shared__ char smem[];
    uint32_t sb = smem_u32(smem);
    int tid = threadIdx.x, wid = tid >> 5, lane = tid & 31;
    int bn = 0, bm = blockIdx.y * BM;
    int m_base = (wid & 1) * 64, n_base = (wid >> 1) * 64;

    float acc[4][8][4];
#pragma unroll
    for (int i = 0; i < 4; i++)
#pragma unroll
        for (int j = 0; j < 8; j++)
#pragma unroll
            for (int q = 0; q < 4; q++) acc[i][j][q] = 0.f;

    const int NIT = KC / BKT;  // 16
    PIPE_PROLOGUE(g_X, g_C, KC)
    for (int it = 0; it < NIT; it++) {
        PIPE_STEP(g_X, g_C, KC, NIT, it)
        compute_stage_f32w(sb + (uint32_t)(it % NSLOT) * STAGE_BYTES, lane, m_base, n_base, acc);
    }

    int r0 = lane >> 2, c0 = (lane & 3) * 2;
#pragma unroll
    for (int mi = 0; mi < 4; mi++) {
        int mg = bm + m_base + mi*16 + r0;
#pragma unroll
        for (int ni = 0; ni < 8; ni++) {
            int cg = bn + n_base + ni*8 + c0;
            {
                size_t o = (size_t)mg*HDIM + cg;
                float2 uv = *(const float2*)&U[o];
                float2 r;
                r.x = uv.x + gelu_tanh(acc[mi][ni][0]);
                r.y = uv.y + gelu_tanh(acc[mi][ni][1]);
                *(float2*)&out[o] = r;
            }
            {
                size_t o = (size_t)(mg+8)*HDIM + cg;
                float2 uv = *(const float2*)&U[o];
                float2 r;
                r.x = uv.x + gelu_tanh(acc[mi][ni][2]);
                r.y = uv.y + gelu_tanh(acc[mi][ni][3]);
                *(float2*)&out[o] = r;
            }
        }
    }
}

// ---------------- launch -----------------------------------------------------
extern "C" void kernel_launch(void* const* d_in, const int* in_sizes, int n_in,
                              void* d_out, int out_size)
{
    const float* u    = (const float*)d_in[0];
    const float* llr  = (const float*)d_in[1];
    const float* lim  = (const float*)d_in[2];
    const float* Btr  = (const float*)d_in[3];
    const float* Bti  = (const float*)d_in[4];
    const float* Ctr  = (const float*)d_in[5];
    const float* Cti  = (const float*)d_in[6];
    const float* ld   = (const float*)d_in[7];
    const float* gmma = (const float*)d_in[8];
    const float* beta = (const float*)d_in[9];
    float* out = (float*)d_out;

    cudaFuncSetAttribute(k_mgemm1, cudaFuncAttributeMaxDynamicSharedMemorySize, SMEM_BYTES);
    cudaFuncSetAttribute(k_mgemm2, cudaFuncAttributeMaxDynamicSharedMemorySize, SMEM_BYTES);

    k_params<<<1, 256>>>(llr, lim, ld);
    k_fill<<<KC*HDIM/256, 256>>>(Btr, Bti, Ctr, Cti);
    k_ln<<<MTOT/8, 256>>>(u, gmma, beta);

    k_mgemm1<<<dim3(KC/BN, MTOT/BM), 256, SMEM_BYTES>>>();

    k_scan_ends<<<dim3(NCHUNK/2, BATCH), 256>>>();
    k_scan_chain<<<BATCH, 256>>>();
    k_scan_write<<<dim3(NCHUNK/2, BATCH), 256>>>();

    k_mgemm2<<<dim3(1, MTOT/BM), 256, SMEM_BYTES>>>(u, out);
}

// round 17
// speedup vs baseline: 1.1371x; 1.1371x over previous
#include <cuda_runtime.h>
#include <cuda_fp16.h>
#include <cstdint>
#include <math.h>

#define BATCH  8
#define LSEQ   4096
#define HDIM   256
#define PDIM   256
#define MTOT   (BATCH*LSEQ)     /* 32768 */
#define CHUNK  64
#define NCHUNK (LSEQ/CHUNK)     /* 64 */
#define KC     512              /* complex-stacked width */

// GEMM tiling (R15 config: BM=128, BN=128, warp tile 64x32)
#define BM 128
#define BN 128
#define BKT 32
#define PADROW 80               /* smem row stride bytes: 40 halves (32 + 8 pad) */
#define T_A 0u
#define T_B 10240u
#define STAGE_BYTES 20480u
#define NSLOT 3
#define SMEM_BYTES (NSLOT*STAGE_BYTES)   /* 61440 */

#define WSCALE   64.0f
#define WUNSCALE 0.015625f

// ---------------- scratch ---------------------------------------------------
__device__ __align__(1024) __half g_h [MTOT*HDIM];
__device__ __align__(1024) __half g_W [KC*HDIM];
__device__ __align__(1024) __half g_C [HDIM*KC];
__device__ __align__(1024) __half g_X [(size_t)MTOT*KC];
__device__ __align__(1024) __half g_bu[(size_t)MTOT*KC];   // fp16, x WSCALE
__device__ float g_ar[PDIM];
__device__ float g_ai[PDIM];
__device__ float g_gr[PDIM];
__device__ float g_gi[PDIM];
__device__ float g_Er[BATCH*NCHUNK*PDIM];
__device__ float g_Ei[BATCH*NCHUNK*PDIM];
__device__ int   g_flag[BATCH*NCHUNK];

// ---------------- PTX helpers (sm_80-class only: valid for .target sm_103) --
__device__ __forceinline__ uint32_t smem_u32(const void* p) {
    uint32_t a;
    asm("{ .reg .u64 t; cvta.to.shared.u64 t, %1; cvt.u32.u64 %0, t; }" : "=r"(a) : "l"(p));
    return a;
}
__device__ __forceinline__ void ldsm4(uint32_t* r, uint32_t addr) {
    asm volatile("ldmatrix.sync.aligned.m8n8.x4.shared.b16 {%0,%1,%2,%3}, [%4];"
        : "=r"(r[0]), "=r"(r[1]), "=r"(r[2]), "=r"(r[3]) : "r"(addr));
}
__device__ __forceinline__ void mma_f16(float* c, const uint32_t* a, const uint32_t* b) {
    asm volatile("mma.sync.aligned.m16n8k16.row.col.f32.f16.f16.f32 "
        "{%0,%1,%2,%3}, {%4,%5,%6,%7}, {%8,%9}, {%0,%1,%2,%3};"
        : "+f"(c[0]), "+f"(c[1]), "+f"(c[2]), "+f"(c[3])
        : "r"(a[0]), "r"(a[1]), "r"(a[2]), "r"(a[3]), "r"(b[0]), "r"(b[1]));
}
__device__ __forceinline__ void mma_f16acc(uint32_t* c, const uint32_t* a, const uint32_t* b) {
    asm volatile("mma.sync.aligned.m16n8k16.row.col.f16.f16.f16.f16 "
        "{%0,%1}, {%2,%3,%4,%5}, {%6,%7}, {%0,%1};"
        : "+r"(c[0]), "+r"(c[1])
        : "r"(a[0]), "r"(a[1]), "r"(a[2]), "r"(a[3]), "r"(b[0]), "r"(b[1]));
}
__device__ __forceinline__ float tanh_fast(float x) {
    float r; asm("tanh.approx.f32 %0, %1;" : "=f"(r) : "f"(x)); return r;
}
#define CP_COMMIT() asm volatile("cp.async.commit_group;" ::: "memory")
#define CP_WAIT(n)  asm volatile("cp.async.wait_group %0;" :: "n"(n) : "memory")

// ---------------- params: lambda_bar + gains only (1 block) ------------------
__global__ void k_params(const float* __restrict__ llr, const float* __restrict__ lim,
                         const float* __restrict__ ld)
{
    int p = threadIdx.x;
    double lr = -exp((double)llr[p]);
    double li = (double)lim[p];
    double d  = exp((double)ld[p]);
    double er = exp(lr * d);
    double ar = er * cos(li * d), ai = er * sin(li * d);
    g_ar[p] = (float)ar;
    g_ai[p] = (float)ai;
    double den = lr*lr + li*li;
    g_gr[p] = (float)(((ar - 1.0)*lr + ai*li) / den);
    g_gi[p] = (float)((ai*lr - (ar - 1.0)*li) / den);
}

// ---------------- parallel W/C fill (512 blocks) + flag reset ----------------
__global__ void k_fill(const float* __restrict__ Btr, const float* __restrict__ Bti,
                       const float* __restrict__ Ctr, const float* __restrict__ Cti)
{
    int idx = blockIdx.x * 256 + threadIdx.x;       // 0 .. 131071
    if (blockIdx.x == 0) {                          // reset lookback flags
        g_flag[threadIdx.x] = 0;
        g_flag[256 + threadIdx.x] = 0;
    }
    {
        int row = idx >> 8, k = idx & 255, pp = row & 255;
        float gr = g_gr[pp], gi = g_gi[pp];
        float br = Btr[pp*HDIM + k], bi = Bti[pp*HDIM + k];
        float w = (row < 256) ? (gr*br - gi*bi) : (gr*bi + gi*br);
        g_W[idx] = __float2half(w * WSCALE);
    }
    {
        int h = idx >> 9, kk = idx & 511;
        float v = (kk < 256) ? Ctr[h*PDIM + kk] : -Cti[h*PDIM + (kk-256)];
        g_C[idx] = __float2half(v);
    }
}

// ---------------- LayerNorm -> fp16 ------------------------------------------
__global__ void k_ln(const float* __restrict__ u, const float* __restrict__ gamma,
                     const float* __restrict__ beta)
{
    int warp = threadIdx.x >> 5, lane = threadIdx.x & 31;
    int row  = blockIdx.x * 8 + warp;
    const float* ur = u + (size_t)row * HDIM;

    float v[8]; float sum = 0.f;
#pragma unroll
    for (int j = 0; j < 8; j++) { v[j] = ur[lane + 32*j]; sum += v[j]; }
#pragma unroll
    for (int o = 16; o; o >>= 1) sum += __shfl_xor_sync(0xffffffffu, sum, o);
    float mu = sum * (1.f/HDIM);

    float ss = 0.f;
#pragma unroll
    for (int j = 0; j < 8; j++) { float dd = v[j]-mu; ss += dd*dd; }
#pragma unroll
    for (int o = 16; o; o >>= 1) ss += __shfl_xor_sync(0xffffffffu, ss, o);
    float inv = rsqrtf(ss * (1.f/HDIM) + 1e-5f);

    size_t base = (size_t)row * HDIM;
#pragma unroll
    for (int j = 0; j < 8; j++) {
        int c = lane + 32*j;
        g_h[base + c] = __float2half((v[j]-mu) * inv * __ldg(&gamma[c]) + __ldg(&beta[c]));
    }
}

// ---------------- async tile loader: 128 rows x 32 fp16 ----------------------
__device__ __forceinline__ void load_tile_async(uint32_t dst_base,
        const __half* __restrict__ src, int row0, int ldk, int k0, int tid)
{
#pragma unroll
    for (int i = 0; i < 2; i++) {
        int ci = tid + i*256;              // 512 chunks of 16B
        int r = ci >> 2, cc = ci & 3;
        const __half* g = src + (size_t)(row0 + r)*ldk + k0 + cc*8;
        uint32_t d = dst_base + (uint32_t)(r*PADROW + cc*16);
        asm volatile("cp.async.cg.shared.global [%0], [%1], 16;" :: "r"(d), "l"(g));
    }
}

// ---------------- BK=32 sub-stage, fp32 acc ----------------------------------
__device__ __forceinline__ void compute_stage_f32(uint32_t sbase, int lane,
                                                  int m_base, int n_base,
                                                  float acc[4][4][4])
{
    int lane16 = lane & 15;
#pragma unroll
    for (int ks = 0; ks < 2; ks++) {
        uint32_t a[4][4], b[8];
#pragma unroll
        for (int mi = 0; mi < 4; mi++) {
            uint32_t off = (uint32_t)((m_base + mi*16 + lane16)*PADROW + ks*32 + (lane>>4)*16);
            ldsm4(a[mi], sbase + T_A + off);
        }
#pragma unroll
        for (int nn = 0; nn < 4; nn += 2) {
            uint32_t off = (uint32_t)((n_base + (nn + (lane>>4))*8 + (lane & 7))*PADROW
                                      + ks*32 + ((lane>>3)&1)*16);
            ldsm4(&b[nn*2], sbase + T_B + off);
        }
#pragma unroll
        for (int mi = 0; mi < 4; mi++)
#pragma unroll
            for (int ni = 0; ni < 4; ni++)
                mma_f16(acc[mi][ni], a[mi], &b[ni*2]);
    }
}

// ---------------- BK=32 sub-stage, fp16 acc ----------------------------------
__device__ __forceinline__ void compute_stage_f16(uint32_t sbase, int lane,
                                                  int m_base, int n_base,
                                                  uint32_t acc[4][4][2])
{
    int lane16 = lane & 15;
#pragma unroll
    for (int ks = 0; ks < 2; ks++) {
        uint32_t a[4][4], b[8];
#pragma unroll
        for (int mi = 0; mi < 4; mi++) {
            uint32_t off = (uint32_t)((m_base + mi*16 + lane16)*PADROW + ks*32 + (lane>>4)*16);
            ldsm4(a[mi], sbase + T_A + off);
        }
#pragma unroll
        for (int nn = 0; nn < 4; nn += 2) {
            uint32_t off = (uint32_t)((n_base + (nn + (lane>>4))*8 + (lane & 7))*PADROW
                                      + ks*32 + ((lane>>3)&1)*16);
            ldsm4(&b[nn*2], sbase + T_B + off);
        }
#pragma unroll
        for (int mi = 0; mi < 4; mi++)
#pragma unroll
            for (int ni = 0; ni < 4; ni++)
                mma_f16acc(acc[mi][ni], a[mi], &b[ni*2]);
    }
}

// ---------------- depth-3 pipeline helpers -----------------------------------
#define PIPE_PROLOGUE(A, B, ldk)                                            \
    load_tile_async(sb + 0*STAGE_BYTES + T_A, A, bm, ldk, 0,   tid);        \
    load_tile_async(sb + 0*STAGE_BYTES + T_B, B, bn, ldk, 0,   tid);        \
    CP_COMMIT();                                                            \
    load_tile_async(sb + 1*STAGE_BYTES + T_A, A, bm, ldk, BKT, tid);        \
    load_tile_async(sb + 1*STAGE_BYTES + T_B, B, bn, ldk, BKT, tid);        \
    CP_COMMIT();

#define PIPE_STEP(A, B, ldk, NIT, it)                                       \
    CP_WAIT(1);                                                             \
    __syncthreads();                                                        \
    {                                                                       \
        int pre = (it) + 2;                                                 \
        if (pre < (NIT)) {                                                  \
            uint32_t ss = sb + (uint32_t)(pre % NSLOT) * STAGE_BYTES;       \
            load_tile_async(ss + T_A, A, bm, ldk, pre*BKT, tid);            \
            load_tile_async(ss + T_B, B, bn, ldk, pre*BKT, tid);            \
        }                                                                   \
        CP_COMMIT();                                                        \
    }

// ---------------- GEMM1: g_bu = h @ W^T (fp16 acc, 3 CTAs/SM) ----------------
__global__ __launch_bounds__(256, 3) void k_mgemm1()
{
    extern __shared__ char smem[];
    uint32_t sb = smem_u32(smem);
    int tid = threadIdx.x, wid = tid >> 5, lane = tid & 31;
    int bn = blockIdx.x * BN, bm = blockIdx.y * BM;
    int m_base = (wid & 1) * 64, n_base = (wid >> 1) * 32;

    uint32_t acc[4][4][2];
#pragma unroll
    for (int i = 0; i < 4; i++)
#pragma unroll
        for (int j = 0; j < 4; j++) { acc[i][j][0] = 0u; acc[i][j][1] = 0u; }

    const int NIT = HDIM / BKT;  // 8
    PIPE_PROLOGUE(g_h, g_W, HDIM)
    for (int it = 0; it < NIT; it++) {
        PIPE_STEP(g_h, g_W, HDIM, NIT, it)
        compute_stage_f16(sb + (uint32_t)(it % NSLOT) * STAGE_BYTES, lane, m_base, n_base, acc);
    }

    int r0 = lane >> 2, c0 = (lane & 3) * 2;
#pragma unroll
    for (int mi = 0; mi < 4; mi++) {
        int mg = bm + m_base + mi*16 + r0;
#pragma unroll
        for (int ni = 0; ni < 4; ni++) {
            int cg = bn + n_base + ni*8 + c0;
            *(uint32_t*)&g_bu[(size_t)mg*KC + cg]     = acc[mi][ni][0];
            *(uint32_t*)&g_bu[(size_t)(mg+8)*KC + cg] = acc[mi][ni][1];
        }
    }
}

// ---------------- fused scan: local scan + decoupled lookback + rescan -------
// grid (NCHUNK, BATCH), 256 threads; thread t owns complex state t.
__global__ __launch_bounds__(256) void k_scan_fused()
{
    int t = threadIdx.x;                 // state index 0..255
    int c = blockIdx.x, b = blockIdx.y;
    int cid = b * NCHUNK + c;

    float ar = g_ar[t], ai = g_ai[t];
    size_t base = ((size_t)b * LSEQ + (size_t)c * CHUNK) * KC;

    // ---- pass 1: chunk-local scan (s0 = 0) ----
    float sr = 0.f, si = 0.f;
#pragma unroll 4
    for (int l = 0; l < CHUNK; l++) {
        size_t o = base + (size_t)l * KC;
        float xr = __half2float(g_bu[o + t]);
        float xi = __half2float(g_bu[o + 256 + t]);
        float nr = fmaf(ar, sr, fmaf(-ai, si, xr));
        float ni = fmaf(ar, si, fmaf( ai, sr, xi));
        sr = nr; si = ni;
    }

    // ---- publish chunk-local end state ----
    g_Er[cid * PDIM + t] = sr;
    g_Ei[cid * PDIM + t] = si;
    __threadfence();
    __syncthreads();
    if (t == 0) atomicExch(&g_flag[cid], 1);

    // ---- lookback: prefix entering chunk c = sum_{j<c} A^{c-1-j} E_j ----
    float pr = 0.f, pi = 0.f;
    if (c > 0) {
        if (t < c) {
            while (atomicAdd(&g_flag[b * NCHUNK + t], 0) == 0) { }
        }
        __syncthreads();
        __threadfence();
        // A = a^64 via 6 complex squarings
        float Ar = ar, Ai = ai;
#pragma unroll
        for (int i = 0; i < 6; i++) { float nr = Ar*Ar - Ai*Ai; Ai = 2.f*Ar*Ai; Ar = nr; }
        for (int j = 0; j < c; j++) {
            int idx = (b * NCHUNK + j) * PDIM + t;
            float er = g_Er[idx], ei = g_Ei[idx];
            float nr = fmaf(Ar, pr, fmaf(-Ai, pi, er));
            pi = fmaf(Ar, pi, fmaf( Ai, pr, ei));
            pr = nr;
        }
    }

    // ---- pass 2: rescan with carry (g_bu re-read hits L2), emit fp16 X ----
    sr = pr; si = pi;
#pragma unroll 4
    for (int l = 0; l < CHUNK; l++) {
        size_t o = base + (size_t)l * KC;
        float xr = __half2float(g_bu[o + t]);
        float xi = __half2float(g_bu[o + 256 + t]);
        float nr = fmaf(ar, sr, fmaf(-ai, si, xr));
        float ni = fmaf(ar, si, fmaf( ai, sr, xi));
        sr = nr; si = ni;
        g_X[o + t]       = __float2half(sr * WUNSCALE);
        g_X[o + 256 + t] = __float2half(si * WUNSCALE);
    }
}

// ---------------- GEMM2: out = u + gelu(X @ C^T) -----------------------------
__device__ __forceinline__ float gelu_tanh(float x)
{
    float x3 = x*x*x;
    float t = tanh_fast(0.7978845608028654f * fmaf(0.044715f, x3, x));
    return 0.5f * x * (1.f + t);
}

__global__ __launch_bounds__(256, 2) void k_mgemm2(const float* __restrict__ U,
                                                   float* __restrict__ out)
{
    extern __shared__ char smem[];
    uint32_t sb = smem_u32(smem);
    int tid = threadIdx.x, wid = tid >> 5, lane = tid & 31;
    int bn = blockIdx.x * BN, bm = blockIdx.y * BM;
    int m_base = (wid & 1) * 64, n_base = (wid >> 1) * 32;

    float acc[4][4][4];
#pragma unroll
    for (int i = 0; i < 4; i++)
#pragma unroll
        for (int j = 0; j < 4; j++)
#pragma unroll
            for (int q = 0; q < 4; q++) acc[i][j][q] = 0.f;

    const int NIT = KC / BKT;  // 16
    PIPE_PROLOGUE(g_X, g_C, KC)
    for (int it = 0; it < NIT; it++) {
        PIPE_STEP(g_X, g_C, KC, NIT, it)
        compute_stage_f32(sb + (uint32_t)(it % NSLOT) * STAGE_BYTES, lane, m_base, n_base, acc);
    }

    int r0 = lane >> 2, c0 = (lane & 3) * 2;
#pragma unroll
    for (int mi = 0; mi < 4; mi++) {
        int mg = bm + m_base + mi*16 + r0;
#pragma unroll
        for (int ni = 0; ni < 4; ni++) {
            int cg = bn + n_base + ni*8 + c0;
            {
                size_t o = (size_t)mg*HDIM + cg;
                float2 uv = *(const float2*)&U[o];
                float2 r;
                r.x = uv.x + gelu_tanh(acc[mi][ni][0]);
                r.y = uv.y + gelu_tanh(acc[mi][ni][1]);
                *(float2*)&out[o] = r;
            }
            {
                size_t o = (size_t)(mg+8)*HDIM + cg;
                float2 uv = *(const float2*)&U[o];
                float2 r;
                r.x = uv.x + gelu_tanh(acc[mi][ni][2]);
                r.y = uv.y + gelu_tanh(acc[mi][ni][3]);
                *(float2*)&out[o] = r;
            }
        }
    }
}

// ---------------- launch -----------------------------------------------------
extern "C" void kernel_launch(void* const* d_in, const int* in_sizes, int n_in,
                              void* d_out, int out_size)
{
    const float* u    = (const float*)d_in[0];
    const float* llr  = (const float*)d_in[1];
    const float* lim  = (const float*)d_in[2];
    const float* Btr  = (const float*)d_in[3];
    const float* Bti  = (const float*)d_in[4];
    const float* Ctr  = (const float*)d_in[5];
    const float* Cti  = (const float*)d_in[6];
    const float* ld   = (const float*)d_in[7];
    const float* gmma = (const float*)d_in[8];
    const float* beta = (const float*)d_in[9];
    float* out = (float*)d_out;

    cudaFuncSetAttribute(k_mgemm1, cudaFuncAttributeMaxDynamicSharedMemorySize, SMEM_BYTES);
    cudaFuncSetAttribute(k_mgemm2, cudaFuncAttributeMaxDynamicSharedMemorySize, SMEM_BYTES);

    k_params<<<1, 256>>>(llr, lim, ld);
    k_fill<<<KC*HDIM/256, 256>>>(Btr, Bti, Ctr, Cti);
    k_ln<<<MTOT/8, 256>>>(u, gmma, beta);

    k_mgemm1<<<dim3(KC/BN, MTOT/BM), 256, SMEM_BYTES>>>();

    k_scan_fused<<<dim3(NCHUNK, BATCH), 256>>>();

    k_mgemm2<<<dim3(HDIM/BN, MTOT/BM), 256, SMEM_BYTES>>>(u, out);
}